// round 1
// baseline (speedup 1.0000x reference)
#include <cuda_runtime.h>
#include <cuda_bf16.h>
#include <cstdint>

#define T_STEPS 12
#define BATCH   64
#define NODE    207
#define HID     16
#define HDIM    6624          // NODE*HID*2
#define IN_DIM  16560         // NODE*HID*5
#define X_DIM   3312          // NODE*HID

// Scratch (device globals: allocation-free rule)
__device__ float g_hz[BATCH * HDIM];       // running hidden state (B, 6624)
__device__ float g_inp[BATCH * IN_DIM];    // (B, 16560) row-major
__device__ float g_inpT[IN_DIM * BATCH];   // (16560, 64)
__device__ float g_pre[BATCH * HDIM];      // (B, 6624)

// ---------------------------------------------------------------------------
// Kernel A: build inp[b, :] from hz, spline slice, small weights.
// One block per (b, n), 256 threads.
// ---------------------------------------------------------------------------
__global__ __launch_bounds__(256) void kA(
    const float* __restrict__ hz, const float* __restrict__ sv_t,
    const float* __restrict__ Wf, const float* __restrict__ bf,
    const float* __restrict__ Wg, const float* __restrict__ bg,
    const float* __restrict__ conv_w, float* __restrict__ inp)
{
    const int blk = blockIdx.x;
    const int b = blk / NODE;
    const int n = blk % NODE;
    const int tid = threadIdx.x;

    __shared__ float sh[HID], sz[HID], sf[HID * 2], sg[HID * HID];

    if (tid < 32) {
        float v = hz[b * HDIM + n * 32 + tid];
        if (tid & 1) sz[tid >> 1] = v;
        else         sh[tid >> 1] = v;
    }
    __syncthreads();

    // g: 256 outputs, one per thread
    {
        float acc = bg[tid];
#pragma unroll
        for (int l = 0; l < HID; l++) acc += sz[l] * Wg[l * 256 + tid];
        sg[tid] = tanhf(acc);
    }
    // f: 32 outputs
    if (tid < 32) {
        float acc = bf[tid];
#pragma unroll
        for (int i = 0; i < HID; i++) acc += sh[i] * Wf[i * 32 + tid];
        sf[tid] = tanhf(acc);
    }
    __syncthreads();

    // fg and writes of hz4 part
    if (tid < 32) {
        const int i = tid >> 1, c = tid & 1;
        float acc = 0.f;
#pragma unroll
        for (int j = 0; j < HID; j++) acc += sg[i * HID + j] * sf[j * 2 + c];
        const int base = b * IN_DIM + X_DIM + n * 64 + i * 4 + c * 2;
        inp[base]     = sf[i * 2 + c];  // s = 0 : f
        inp[base + 1] = acc;            // s = 1 : fg
    }
    // x part: x[b, hc*NODE + n] = conv_w[hc] * sv[b, n, 1]
    if (tid < HID) {
        float v = sv_t[(b * NODE + n) * 2 + 1];
        inp[b * IN_DIM + tid * NODE + n] = conv_w[tid] * v;
    }
}

// ---------------------------------------------------------------------------
// Kernel T: transpose inp (64,16560) -> inpT (16560,64)
// ---------------------------------------------------------------------------
__global__ __launch_bounds__(256) void kT(
    const float* __restrict__ inp, float* __restrict__ inpT)
{
    __shared__ float tile[32][33];
    const int i0 = blockIdx.x * 32;   // K dim
    const int b0 = blockIdx.y * 32;   // batch dim
    const int x = threadIdx.x, y = threadIdx.y;

#pragma unroll
    for (int r = 0; r < 32; r += 8) {
        const int b = b0 + y + r, i = i0 + x;
        if (i < IN_DIM) tile[y + r][x] = inp[b * IN_DIM + i];
    }
    __syncthreads();
#pragma unroll
    for (int r = 0; r < 32; r += 8) {
        const int i = i0 + y + r, b = b0 + x;
        if (i < IN_DIM) inpT[i * BATCH + b] = tile[x][y + r];
    }
}

// ---------------------------------------------------------------------------
// Kernel B: pre[b,o] = b_ih[o] + sum_i inpT[i,b] * W_ih[o,i]
// Grid 207 blocks; block = 256 thr = (64 batch) x (4 groups of 8 outputs).
// ---------------------------------------------------------------------------
__global__ __launch_bounds__(256) void kB(
    const float* __restrict__ inpT, const float* __restrict__ Wih,
    const float* __restrict__ bih, float* __restrict__ pre)
{
    const int tid = threadIdx.x;
    const int b  = tid & 63;
    const int jg = tid >> 6;                 // 0..3
    const int o0 = blockIdx.x * 32 + jg * 8; // 8 outputs per thread

    const float* w0 = Wih + (size_t)o0 * IN_DIM;

    float acc[8];
#pragma unroll
    for (int k = 0; k < 8; k++) acc[k] = 0.f;

    for (int i = 0; i < IN_DIM; i += 4) {
        const float x0 = inpT[(i    ) * BATCH + b];
        const float x1 = inpT[(i + 1) * BATCH + b];
        const float x2 = inpT[(i + 2) * BATCH + b];
        const float x3 = inpT[(i + 3) * BATCH + b];
#pragma unroll
        for (int k = 0; k < 8; k++) {
            const float4 w = *reinterpret_cast<const float4*>(w0 + (size_t)k * IN_DIM + i);
            acc[k] += w.x * x0 + w.y * x1 + w.z * x2 + w.w * x3;
        }
    }
#pragma unroll
    for (int k = 0; k < 8; k++)
        pre[b * HDIM + o0 + k] = acc[k] + bih[o0 + k];
}

// ---------------------------------------------------------------------------
// Kernel C: one recurrent step: hout[o] = tanh(pre[o] + b_hh[o] + Whh[o,:].h)
// Warp per output row; 8 rows per block; grid 828.
// hprev == nullptr encodes the zero initial state (b == 0).
// ---------------------------------------------------------------------------
__global__ __launch_bounds__(256) void kC(
    const float* __restrict__ Whh, const float* __restrict__ hprev,
    const float* __restrict__ pre_b, const float* __restrict__ bhh,
    float* __restrict__ hout)
{
    const int warp = threadIdx.x >> 5;
    const int lane = threadIdx.x & 31;
    const int o = blockIdx.x * 8 + warp;

    float acc = 0.f;
    if (hprev) {
        const float4* wrow = reinterpret_cast<const float4*>(Whh + (size_t)o * HDIM);
        const float4* h4   = reinterpret_cast<const float4*>(hprev);
        for (int k = lane; k < HDIM / 4; k += 32) {  // 1656 float4s
            const float4 w = wrow[k];
            const float4 h = __ldg(&h4[k]);
            acc += w.x * h.x + w.y * h.y + w.z * h.z + w.w * h.w;
        }
    }
#pragma unroll
    for (int s = 16; s; s >>= 1) acc += __shfl_xor_sync(0xffffffffu, acc, s);

    if (lane == 0) hout[o] = tanhf(acc + pre_b[o] + bhh[o]);
}

// ---------------------------------------------------------------------------
extern "C" void kernel_launch(void* const* d_in, const int* in_sizes, int n_in,
                              void* d_out, int out_size)
{
    const float* sv    = (const float*)d_in[0];   // (T,B,NODE,2)
    const float* init0 = (const float*)d_in[1];   // (B,HDIM)
    const float* Wf    = (const float*)d_in[2];   // (16,32)
    const float* bf    = (const float*)d_in[3];   // (32)
    const float* Wg    = (const float*)d_in[4];   // (16,256)
    const float* bg    = (const float*)d_in[5];   // (256)
    const float* cw    = (const float*)d_in[6];   // (16)
    const float* Wih   = (const float*)d_in[7];   // (6624,16560)
    const float* bih   = (const float*)d_in[8];   // (6624)
    const float* Whh   = (const float*)d_in[9];   // (6624,6624)
    const float* bhh   = (const float*)d_in[10];  // (6624)

    float *hz, *inp, *inpT, *pre;
    cudaGetSymbolAddress((void**)&hz,   g_hz);
    cudaGetSymbolAddress((void**)&inp,  g_inp);
    cudaGetSymbolAddress((void**)&inpT, g_inpT);
    cudaGetSymbolAddress((void**)&pre,  g_pre);

    cudaMemcpyAsync(hz, init0, (size_t)BATCH * HDIM * sizeof(float),
                    cudaMemcpyDeviceToDevice);

    for (int t = 0; t < T_STEPS; t++) {
        kA<<<BATCH * NODE, 256>>>(hz, sv + (size_t)t * BATCH * NODE * 2,
                                  Wf, bf, Wg, bg, cw, inp);
        {
            dim3 tb(32, 8), tg((IN_DIM + 31) / 32, BATCH / 32);
            kT<<<tg, tb>>>(inp, inpT);
        }
        kB<<<HDIM / 32, 256>>>(inpT, Wih, bih, pre);

        for (int b = 0; b < BATCH; b++) {
            kC<<<HDIM / 8, 256>>>(Whh,
                                  b ? (hz + (size_t)(b - 1) * HDIM) : nullptr,
                                  pre + (size_t)b * HDIM,
                                  bhh,
                                  hz + (size_t)b * HDIM);
        }
    }

    cudaMemcpyAsync(d_out, hz, (size_t)BATCH * HDIM * sizeof(float),
                    cudaMemcpyDeviceToDevice);
}

// round 3
// speedup vs baseline: 1.1194x; 1.1194x over previous
#include <cuda_runtime.h>
#include <cstdint>

#define T_STEPS 12
#define BATCH   64
#define NODE    207
#define HID     16
#define HDIM    6624          // NODE*HID*2
#define IN_DIM  16560         // NODE*HID*5
#define X_DIM   3312          // NODE*HID
#define WSTRIDE 6656          // padded row stride (1664 float4 = 52*32)
#define NB      276           // persistent grid: 276 * 24 rows = 6624

// Scratch (device globals: allocation-free rule)
__device__ float  g_hz[BATCH * HDIM];       // per-inner-step hidden states
__device__ float  g_inp[BATCH * IN_DIM];    // (B, 16560) row-major
__device__ float  g_inpT[IN_DIM * BATCH];   // (16560, 64)
__device__ float  g_pre[BATCH * HDIM];      // (B, 6624)
__device__ float  g_w[HDIM * WSTRIDE];      // padded fp32 W_hh (~176 MB)
__device__ unsigned g_bar[2];               // [0]=count (monotone), [1]=phase

// ---------------------------------------------------------------------------
// Kernel H: W_hh -> padded copy (zero pad to WSTRIDE)
// ---------------------------------------------------------------------------
__global__ __launch_bounds__(256) void kH(const float* __restrict__ W)
{
    const int o = blockIdx.x;
    for (int i = threadIdx.x; i < WSTRIDE; i += 256)
        g_w[(size_t)o * WSTRIDE + i] = (i < HDIM) ? W[(size_t)o * HDIM + i] : 0.f;
}

// ---------------------------------------------------------------------------
// Kernel A: build inp[b, :] from hz, spline slice, small weights.
// ---------------------------------------------------------------------------
__global__ __launch_bounds__(256) void kA(
    const float* __restrict__ hz, const float* __restrict__ sv_t,
    const float* __restrict__ Wf, const float* __restrict__ bf,
    const float* __restrict__ Wg, const float* __restrict__ bg,
    const float* __restrict__ conv_w, float* __restrict__ inp)
{
    const int blk = blockIdx.x;
    const int b = blk / NODE;
    const int n = blk % NODE;
    const int tid = threadIdx.x;

    __shared__ float sh[HID], sz[HID], sf[HID * 2], sg[HID * HID];

    if (tid < 32) {
        float v = hz[b * HDIM + n * 32 + tid];
        if (tid & 1) sz[tid >> 1] = v;
        else         sh[tid >> 1] = v;
    }
    __syncthreads();

    {
        float acc = bg[tid];
#pragma unroll
        for (int l = 0; l < HID; l++) acc += sz[l] * Wg[l * 256 + tid];
        sg[tid] = tanhf(acc);
    }
    if (tid < 32) {
        float acc = bf[tid];
#pragma unroll
        for (int i = 0; i < HID; i++) acc += sh[i] * Wf[i * 32 + tid];
        sf[tid] = tanhf(acc);
    }
    __syncthreads();

    if (tid < 32) {
        const int i = tid >> 1, c = tid & 1;
        float acc = 0.f;
#pragma unroll
        for (int j = 0; j < HID; j++) acc += sg[i * HID + j] * sf[j * 2 + c];
        const int base = b * IN_DIM + X_DIM + n * 64 + i * 4 + c * 2;
        inp[base]     = sf[i * 2 + c];
        inp[base + 1] = acc;
    }
    if (tid < HID) {
        float v = sv_t[(b * NODE + n) * 2 + 1];
        inp[b * IN_DIM + tid * NODE + n] = conv_w[tid] * v;
    }
}

// ---------------------------------------------------------------------------
// Kernel T: transpose inp (64,16560) -> inpT (16560,64)
// ---------------------------------------------------------------------------
__global__ __launch_bounds__(256) void kT(
    const float* __restrict__ inp, float* __restrict__ inpT)
{
    __shared__ float tile[32][33];
    const int i0 = blockIdx.x * 32;
    const int b0 = blockIdx.y * 32;
    const int x = threadIdx.x, y = threadIdx.y;

#pragma unroll
    for (int r = 0; r < 32; r += 8) {
        const int b = b0 + y + r, i = i0 + x;
        if (i < IN_DIM) tile[y + r][x] = inp[b * IN_DIM + i];
    }
    __syncthreads();
#pragma unroll
    for (int r = 0; r < 32; r += 8) {
        const int i = i0 + y + r, b = b0 + x;
        if (i < IN_DIM) inpT[i * BATCH + b] = tile[x][y + r];
    }
}

// ---------------------------------------------------------------------------
// Kernel B: pre[b,o] = b_ih[o] + sum_i inpT[i,b] * W_ih[o,i]
// Grid 414; block = 256 thr = (64 batch) x (4 groups of 4 outputs).
// ---------------------------------------------------------------------------
__global__ __launch_bounds__(256) void kB(
    const float* __restrict__ inpT, const float* __restrict__ Wih,
    const float* __restrict__ bih, float* __restrict__ pre)
{
    const int tid = threadIdx.x;
    const int b  = tid & 63;
    const int jg = tid >> 6;                 // 0..3
    const int o0 = blockIdx.x * 16 + jg * 4; // 4 outputs per thread

    const float* w0 = Wih + (size_t)o0 * IN_DIM;

    float acc[4];
#pragma unroll
    for (int k = 0; k < 4; k++) acc[k] = 0.f;

    for (int i = 0; i < IN_DIM; i += 4) {
        const float x0 = inpT[(i    ) * BATCH + b];
        const float x1 = inpT[(i + 1) * BATCH + b];
        const float x2 = inpT[(i + 2) * BATCH + b];
        const float x3 = inpT[(i + 3) * BATCH + b];
#pragma unroll
        for (int k = 0; k < 4; k++) {
            const float4 w = *reinterpret_cast<const float4*>(w0 + (size_t)k * IN_DIM + i);
            acc[k] += w.x * x0 + w.y * x1 + w.z * x2 + w.w * x3;
        }
    }
#pragma unroll
    for (int k = 0; k < 4; k++)
        pre[b * HDIM + o0 + k] = acc[k] + bih[o0 + k];
}

// ---------------------------------------------------------------------------
// Kernel C (persistent, fp32): all 64 recurrent steps of one outer t.
// 276 blocks x 256 threads (2 CTAs/SM), 24 rows/block, 3 rows/warp.
// Inner loop: 52 lane-strided float4 chunks per row, unrolled x2 for MLP.
// Grid barrier: monotone count g_bar[0], phase g_bar[1]; index t*64+step+1.
// ---------------------------------------------------------------------------
__global__ __launch_bounds__(256, 2) void kC_persist(
    const float* __restrict__ W, const float* __restrict__ pre,
    const float* __restrict__ bhh, float* __restrict__ hz, int t)
{
    __shared__ float sh[WSTRIDE];
    const int tid  = threadIdx.x;
    const int warp = tid >> 5;
    const int lane = tid & 31;
    const int rbase = blockIdx.x * 24 + warp * 3;

    const float4* W0 = reinterpret_cast<const float4*>(W + (size_t)(rbase    ) * WSTRIDE);
    const float4* W1 = reinterpret_cast<const float4*>(W + (size_t)(rbase + 1) * WSTRIDE);
    const float4* W2 = reinterpret_cast<const float4*>(W + (size_t)(rbase + 2) * WSTRIDE);
    const float4* H4 = reinterpret_cast<const float4*>(sh);

    if (tid < WSTRIDE - HDIM) sh[HDIM + tid] = 0.f;   // zero smem pad once

    for (int step = 0; step < BATCH; step++) {
        float a0 = 0.f, a1 = 0.f, a2 = 0.f;

        if (step > 0) {
            // stage h_{step-1} into smem (L2-coherent loads: other SMs wrote it)
            const float* hp = hz + (size_t)(step - 1) * HDIM;
            for (int i = tid; i < HDIM; i += 256) sh[i] = __ldcg(hp + i);
            __syncthreads();

#pragma unroll 1
            for (int c = 0; c < 52; c += 2) {
                const int k0 = c * 32 + lane;
                const int k1 = k0 + 32;
                const float4 wa0 = W0[k0], wa1 = W0[k1];
                const float4 wb0 = W1[k0], wb1 = W1[k1];
                const float4 wc0 = W2[k0], wc1 = W2[k1];
                const float4 h0  = H4[k0], h1  = H4[k1];
                a0 += wa0.x*h0.x + wa0.y*h0.y + wa0.z*h0.z + wa0.w*h0.w;
                a1 += wb0.x*h0.x + wb0.y*h0.y + wb0.z*h0.z + wb0.w*h0.w;
                a2 += wc0.x*h0.x + wc0.y*h0.y + wc0.z*h0.z + wc0.w*h0.w;
                a0 += wa1.x*h1.x + wa1.y*h1.y + wa1.z*h1.z + wa1.w*h1.w;
                a1 += wb1.x*h1.x + wb1.y*h1.y + wb1.z*h1.z + wb1.w*h1.w;
                a2 += wc1.x*h1.x + wc1.y*h1.y + wc1.z*h1.z + wc1.w*h1.w;
            }
        }

#pragma unroll
        for (int s = 16; s; s >>= 1) {
            a0 += __shfl_xor_sync(0xffffffffu, a0, s);
            a1 += __shfl_xor_sync(0xffffffffu, a1, s);
            a2 += __shfl_xor_sync(0xffffffffu, a2, s);
        }
        if (lane == 0) {
            const float* pre_b = pre + (size_t)step * HDIM;
            float* hout = hz + (size_t)step * HDIM;
            __stcg(hout + rbase    , tanhf(a0 + pre_b[rbase    ] + bhh[rbase    ]));
            __stcg(hout + rbase + 1, tanhf(a1 + pre_b[rbase + 1] + bhh[rbase + 1]));
            __stcg(hout + rbase + 2, tanhf(a2 + pre_b[rbase + 2] + bhh[rbase + 2]));
        }

        // grid barrier (also protects smem WAR for next step's staging)
        __threadfence();
        __syncthreads();
        if (tid == 0) {
            const unsigned k = (unsigned)(t * BATCH + step + 1);
            const unsigned old = atomicAdd(&g_bar[0], 1u);
            if (old == k * NB - 1u) {
                atomicExch(&g_bar[1], k);
            } else {
                while (atomicAdd(&g_bar[1], 0u) < k) __nanosleep(64);
            }
        }
        __syncthreads();
    }
}

// ---------------------------------------------------------------------------
extern "C" void kernel_launch(void* const* d_in, const int* in_sizes, int n_in,
                              void* d_out, int out_size)
{
    const float* sv    = (const float*)d_in[0];   // (T,B,NODE,2)
    const float* init0 = (const float*)d_in[1];   // (B,HDIM)
    const float* Wf    = (const float*)d_in[2];
    const float* bf    = (const float*)d_in[3];
    const float* Wg    = (const float*)d_in[4];
    const float* bg    = (const float*)d_in[5];
    const float* cw    = (const float*)d_in[6];
    const float* Wih   = (const float*)d_in[7];   // (6624,16560)
    const float* bih   = (const float*)d_in[8];
    const float* Whh   = (const float*)d_in[9];   // (6624,6624)
    const float* bhh   = (const float*)d_in[10];

    float *hz, *inp, *inpT, *pre, *wpad;
    unsigned* bar;
    cudaGetSymbolAddress((void**)&hz,   g_hz);
    cudaGetSymbolAddress((void**)&inp,  g_inp);
    cudaGetSymbolAddress((void**)&inpT, g_inpT);
    cudaGetSymbolAddress((void**)&pre,  g_pre);
    cudaGetSymbolAddress((void**)&wpad, g_w);
    cudaGetSymbolAddress((void**)&bar,  g_bar);

    cudaMemsetAsync(bar, 0, 2 * sizeof(unsigned));
    kH<<<HDIM, 256>>>(Whh);
    cudaMemcpyAsync(hz, init0, (size_t)BATCH * HDIM * sizeof(float),
                    cudaMemcpyDeviceToDevice);

    for (int t = 0; t < T_STEPS; t++) {
        kA<<<BATCH * NODE, 256>>>(hz, sv + (size_t)t * BATCH * NODE * 2,
                                  Wf, bf, Wg, bg, cw, inp);
        {
            dim3 tb(32, 8), tg((IN_DIM + 31) / 32, BATCH / 32);
            kT<<<tg, tb>>>(inp, inpT);
        }
        kB<<<HDIM / 16, 256>>>(inpT, Wih, bih, pre);

        kC_persist<<<NB, 256>>>(wpad, pre, bhh, hz, t);
    }

    cudaMemcpyAsync(d_out, hz, (size_t)BATCH * HDIM * sizeof(float),
                    cudaMemcpyDeviceToDevice);
}

// round 4
// speedup vs baseline: 1.3926x; 1.2440x over previous
#include <cuda_runtime.h>
#include <cstdint>

#define T_STEPS 12
#define BATCH   64
#define NODE    207
#define HID     16
#define HDIM    6624          // NODE*HID*2
#define IN_DIM  16560         // NODE*HID*5
#define X_DIM   3312          // NODE*HID
#define WSTRIDE 6656          // padded row stride (1664 float4)
#define NB      276           // persistent grid
#define NCHUNK  276           // work-stealing chunks (24 rows each)
#define KRES4   1024          // resident float4s per row (4096 floats = 108.5 MB total)
#define KTOT4   1664          // total float4s per row

// Scratch (device globals: allocation-free rule)
__device__ float  g_hz[BATCH * HDIM];
__device__ float  g_inp[BATCH * IN_DIM];
__device__ float  g_inpT[IN_DIM * BATCH];
__device__ float  g_pre[BATCH * HDIM];
__device__ float  g_w[HDIM * WSTRIDE];      // padded fp32 W_hh (~176 MB)
__device__ unsigned g_bar[2];               // [0]=count (monotone), [1]=phase
__device__ unsigned g_ctr[T_STEPS * BATCH]; // per-step chunk counters

// ---------------------------------------------------------------------------
__global__ __launch_bounds__(256) void kH(const float* __restrict__ W)
{
    const int o = blockIdx.x;
    for (int i = threadIdx.x; i < WSTRIDE; i += 256)
        g_w[(size_t)o * WSTRIDE + i] = (i < HDIM) ? W[(size_t)o * HDIM + i] : 0.f;
}

// ---------------------------------------------------------------------------
__global__ __launch_bounds__(256) void kA(
    const float* __restrict__ hz, const float* __restrict__ sv_t,
    const float* __restrict__ Wf, const float* __restrict__ bf,
    const float* __restrict__ Wg, const float* __restrict__ bg,
    const float* __restrict__ conv_w, float* __restrict__ inp)
{
    const int blk = blockIdx.x;
    const int b = blk / NODE;
    const int n = blk % NODE;
    const int tid = threadIdx.x;

    __shared__ float sh[HID], sz[HID], sf[HID * 2], sg[HID * HID];

    if (tid < 32) {
        float v = hz[b * HDIM + n * 32 + tid];
        if (tid & 1) sz[tid >> 1] = v;
        else         sh[tid >> 1] = v;
    }
    __syncthreads();

    {
        float acc = bg[tid];
#pragma unroll
        for (int l = 0; l < HID; l++) acc += sz[l] * Wg[l * 256 + tid];
        sg[tid] = tanhf(acc);
    }
    if (tid < 32) {
        float acc = bf[tid];
#pragma unroll
        for (int i = 0; i < HID; i++) acc += sh[i] * Wf[i * 32 + tid];
        sf[tid] = tanhf(acc);
    }
    __syncthreads();

    if (tid < 32) {
        const int i = tid >> 1, c = tid & 1;
        float acc = 0.f;
#pragma unroll
        for (int j = 0; j < HID; j++) acc += sg[i * HID + j] * sf[j * 2 + c];
        const int base = b * IN_DIM + X_DIM + n * 64 + i * 4 + c * 2;
        inp[base]     = sf[i * 2 + c];
        inp[base + 1] = acc;
    }
    if (tid < HID) {
        float v = sv_t[(b * NODE + n) * 2 + 1];
        inp[b * IN_DIM + tid * NODE + n] = conv_w[tid] * v;
    }
}

// ---------------------------------------------------------------------------
__global__ __launch_bounds__(256) void kT(
    const float* __restrict__ inp, float* __restrict__ inpT)
{
    __shared__ float tile[32][33];
    const int i0 = blockIdx.x * 32;
    const int b0 = blockIdx.y * 32;
    const int x = threadIdx.x, y = threadIdx.y;

#pragma unroll
    for (int r = 0; r < 32; r += 8) {
        const int b = b0 + y + r, i = i0 + x;
        if (i < IN_DIM) tile[y + r][x] = inp[b * IN_DIM + i];
    }
    __syncthreads();
#pragma unroll
    for (int r = 0; r < 32; r += 8) {
        const int i = i0 + y + r, b = b0 + x;
        if (i < IN_DIM) inpT[i * BATCH + b] = tile[x][y + r];
    }
}

// ---------------------------------------------------------------------------
// Kernel B: Wih read with __ldcs (evict-first) to protect the resident W_hh
// set in L2 between kC_persist launches.
// ---------------------------------------------------------------------------
__global__ __launch_bounds__(256) void kB(
    const float* __restrict__ inpT, const float* __restrict__ Wih,
    const float* __restrict__ bih, float* __restrict__ pre)
{
    const int tid = threadIdx.x;
    const int b  = tid & 63;
    const int jg = tid >> 6;
    const int o0 = blockIdx.x * 16 + jg * 4;

    const float* w0 = Wih + (size_t)o0 * IN_DIM;

    float acc[4];
#pragma unroll
    for (int k = 0; k < 4; k++) acc[k] = 0.f;

    for (int i = 0; i < IN_DIM; i += 4) {
        const float x0 = inpT[(i    ) * BATCH + b];
        const float x1 = inpT[(i + 1) * BATCH + b];
        const float x2 = inpT[(i + 2) * BATCH + b];
        const float x3 = inpT[(i + 3) * BATCH + b];
#pragma unroll
        for (int k = 0; k < 4; k++) {
            const float4 w = __ldcs(reinterpret_cast<const float4*>(
                                        w0 + (size_t)k * IN_DIM + i));
            acc[k] += w.x * x0 + w.y * x1 + w.z * x2 + w.w * x3;
        }
    }
#pragma unroll
    for (int k = 0; k < 4; k++)
        pre[b * HDIM + o0 + k] = acc[k] + bih[o0 + k];
}

// ---------------------------------------------------------------------------
// Kernel C (persistent, fp32, work-stealing + L2-resident column split).
// 276 blocks x 256 threads (2 CTAs/SM). Per step: stage h to smem, then
// steal 24-row chunks via per-step atomic counter. Columns [0,4096) read
// normally (L2-resident, 108.5 MB); columns [4096,6656) read with __ldcs.
// Grid barrier per step: monotone count g_bar[0], phase g_bar[1].
// ---------------------------------------------------------------------------
__global__ __launch_bounds__(256, 2) void kC_persist(
    const float* __restrict__ W, const float* __restrict__ pre,
    const float* __restrict__ bhh, float* __restrict__ hz, int t)
{
    __shared__ float sh[WSTRIDE];
    __shared__ int s_chunk;
    const int tid  = threadIdx.x;
    const int warp = tid >> 5;
    const int lane = tid & 31;
    const float4* H4 = reinterpret_cast<const float4*>(sh);

    if (tid < WSTRIDE - HDIM) sh[HDIM + tid] = 0.f;   // zero smem pad once

    for (int step = 0; step < BATCH; step++) {
        if (step > 0) {
            const float* hp = hz + (size_t)(step - 1) * HDIM;
            for (int i = tid; i < HDIM; i += 256) sh[i] = __ldcg(hp + i);
        }
        __syncthreads();

        const int idx = t * BATCH + step;
        for (;;) {
            if (tid == 0) s_chunk = (int)atomicAdd(&g_ctr[idx], 1u);
            __syncthreads();
            const int c = s_chunk;
            __syncthreads();
            if (c >= NCHUNK) break;

            const int rbase = c * 24 + warp * 3;
            const float4* W0 = reinterpret_cast<const float4*>(W + (size_t)(rbase    ) * WSTRIDE);
            const float4* W1 = reinterpret_cast<const float4*>(W + (size_t)(rbase + 1) * WSTRIDE);
            const float4* W2 = reinterpret_cast<const float4*>(W + (size_t)(rbase + 2) * WSTRIDE);

            float a0 = 0.f, a1 = 0.f, a2 = 0.f;
            if (step > 0) {
                // resident columns: 1024 float4 per row, lane-strided, x2 unroll
#pragma unroll 1
                for (int cc = 0; cc < 32; cc += 2) {
                    const int k0 = cc * 32 + lane, k1 = k0 + 32;
                    const float4 wa0 = W0[k0], wa1 = W0[k1];
                    const float4 wb0 = W1[k0], wb1 = W1[k1];
                    const float4 wc0 = W2[k0], wc1 = W2[k1];
                    const float4 h0  = H4[k0], h1  = H4[k1];
                    a0 += wa0.x*h0.x + wa0.y*h0.y + wa0.z*h0.z + wa0.w*h0.w;
                    a1 += wb0.x*h0.x + wb0.y*h0.y + wb0.z*h0.z + wb0.w*h0.w;
                    a2 += wc0.x*h0.x + wc0.y*h0.y + wc0.z*h0.z + wc0.w*h0.w;
                    a0 += wa1.x*h1.x + wa1.y*h1.y + wa1.z*h1.z + wa1.w*h1.w;
                    a1 += wb1.x*h1.x + wb1.y*h1.y + wb1.z*h1.z + wb1.w*h1.w;
                    a2 += wc1.x*h1.x + wc1.y*h1.y + wc1.z*h1.z + wc1.w*h1.w;
                }
                // streaming columns: 640 float4 per row, evict-first
#pragma unroll 1
                for (int cc = 0; cc < 20; cc += 2) {
                    const int k0 = KRES4 + cc * 32 + lane, k1 = k0 + 32;
                    const float4 wa0 = __ldcs(&W0[k0]), wa1 = __ldcs(&W0[k1]);
                    const float4 wb0 = __ldcs(&W1[k0]), wb1 = __ldcs(&W1[k1]);
                    const float4 wc0 = __ldcs(&W2[k0]), wc1 = __ldcs(&W2[k1]);
                    const float4 h0  = H4[k0], h1  = H4[k1];
                    a0 += wa0.x*h0.x + wa0.y*h0.y + wa0.z*h0.z + wa0.w*h0.w;
                    a1 += wb0.x*h0.x + wb0.y*h0.y + wb0.z*h0.z + wb0.w*h0.w;
                    a2 += wc0.x*h0.x + wc0.y*h0.y + wc0.z*h0.z + wc0.w*h0.w;
                    a0 += wa1.x*h1.x + wa1.y*h1.y + wa1.z*h1.z + wa1.w*h1.w;
                    a1 += wb1.x*h1.x + wb1.y*h1.y + wb1.z*h1.z + wb1.w*h1.w;
                    a2 += wc1.x*h1.x + wc1.y*h1.y + wc1.z*h1.z + wc1.w*h1.w;
                }
            }

#pragma unroll
            for (int s = 16; s; s >>= 1) {
                a0 += __shfl_xor_sync(0xffffffffu, a0, s);
                a1 += __shfl_xor_sync(0xffffffffu, a1, s);
                a2 += __shfl_xor_sync(0xffffffffu, a2, s);
            }
            if (lane == 0) {
                const float* pre_b = pre + (size_t)step * HDIM;
                float* hout = hz + (size_t)step * HDIM;
                __stcg(hout + rbase    , tanhf(a0 + pre_b[rbase    ] + bhh[rbase    ]));
                __stcg(hout + rbase + 1, tanhf(a1 + pre_b[rbase + 1] + bhh[rbase + 1]));
                __stcg(hout + rbase + 2, tanhf(a2 + pre_b[rbase + 2] + bhh[rbase + 2]));
            }
        }

        // grid barrier (also protects smem WAR for next step's staging)
        __threadfence();
        __syncthreads();
        if (tid == 0) {
            const unsigned k = (unsigned)(t * BATCH + step + 1);
            const unsigned old = atomicAdd(&g_bar[0], 1u);
            if (old == k * NB - 1u) {
                atomicExch(&g_bar[1], k);
            } else {
                while (atomicAdd(&g_bar[1], 0u) < k) __nanosleep(64);
            }
        }
        __syncthreads();
    }
}

// ---------------------------------------------------------------------------
extern "C" void kernel_launch(void* const* d_in, const int* in_sizes, int n_in,
                              void* d_out, int out_size)
{
    const float* sv    = (const float*)d_in[0];
    const float* init0 = (const float*)d_in[1];
    const float* Wf    = (const float*)d_in[2];
    const float* bf    = (const float*)d_in[3];
    const float* Wg    = (const float*)d_in[4];
    const float* bg    = (const float*)d_in[5];
    const float* cw    = (const float*)d_in[6];
    const float* Wih   = (const float*)d_in[7];
    const float* bih   = (const float*)d_in[8];
    const float* Whh   = (const float*)d_in[9];
    const float* bhh   = (const float*)d_in[10];

    float *hz, *inp, *inpT, *pre, *wpad;
    unsigned *bar, *ctr;
    cudaGetSymbolAddress((void**)&hz,   g_hz);
    cudaGetSymbolAddress((void**)&inp,  g_inp);
    cudaGetSymbolAddress((void**)&inpT, g_inpT);
    cudaGetSymbolAddress((void**)&pre,  g_pre);
    cudaGetSymbolAddress((void**)&wpad, g_w);
    cudaGetSymbolAddress((void**)&bar,  g_bar);
    cudaGetSymbolAddress((void**)&ctr,  g_ctr);

    cudaMemsetAsync(bar, 0, 2 * sizeof(unsigned));
    cudaMemsetAsync(ctr, 0, T_STEPS * BATCH * sizeof(unsigned));
    kH<<<HDIM, 256>>>(Whh);
    cudaMemcpyAsync(hz, init0, (size_t)BATCH * HDIM * sizeof(float),
                    cudaMemcpyDeviceToDevice);

    for (int t = 0; t < T_STEPS; t++) {
        kA<<<BATCH * NODE, 256>>>(hz, sv + (size_t)t * BATCH * NODE * 2,
                                  Wf, bf, Wg, bg, cw, inp);
        {
            dim3 tb(32, 8), tg((IN_DIM + 31) / 32, BATCH / 32);
            kT<<<tg, tb>>>(inp, inpT);
        }
        kB<<<HDIM / 16, 256>>>(inpT, Wih, bih, pre);

        kC_persist<<<NB, 256>>>(wpad, pre, bhh, hz, t);
    }

    cudaMemcpyAsync(d_out, hz, (size_t)BATCH * HDIM * sizeof(float),
                    cudaMemcpyDeviceToDevice);
}

// round 5
// speedup vs baseline: 1.5289x; 1.0979x over previous
#include <cuda_runtime.h>
#include <cstdint>

#define T_STEPS 12
#define BATCH   64
#define NODE    207
#define HID     16
#define HDIM    6624          // NODE*HID*2
#define IN_DIM  16560         // NODE*HID*5
#define X_DIM   3312          // NODE*HID
#define WSTRIDE 6656          // padded row stride (1664 float4)
#define NB      138           // persistent grid: 138 blocks * 48 rows = 6624
#define ROWS_PB 48
#define CSM4    256           // smem-cached float4 per row  (cols [0,1024))
#define CL24    512           // L2-resident float4 per row  (cols [1024,3072))
#define CST4    896           // streamed float4 per row     (cols [3072,6656))
// dynamic smem: h (WSTRIDE floats) + cache (48*1024 floats)
#define SMEM_FLOATS (WSTRIDE + ROWS_PB * CSM4 * 4)
#define SMEM_BYTES  (SMEM_FLOATS * 4)

// Scratch (device globals: allocation-free rule)
__device__ float  g_hz[BATCH * HDIM];
__device__ float  g_inp[BATCH * IN_DIM];
__device__ float  g_inpT[IN_DIM * BATCH];
__device__ float  g_pre[BATCH * HDIM];
__device__ float  g_w[HDIM * WSTRIDE];      // padded fp32 W_hh (~176 MB)
__device__ unsigned g_bar[2];               // [0]=count (monotone), [1]=phase

// ---------------------------------------------------------------------------
__global__ __launch_bounds__(256) void kH(const float* __restrict__ W)
{
    const int o = blockIdx.x;
    for (int i = threadIdx.x; i < WSTRIDE; i += 256)
        g_w[(size_t)o * WSTRIDE + i] = (i < HDIM) ? W[(size_t)o * HDIM + i] : 0.f;
}

// ---------------------------------------------------------------------------
__global__ __launch_bounds__(256) void kA(
    const float* __restrict__ hz, const float* __restrict__ sv_t,
    const float* __restrict__ Wf, const float* __restrict__ bf,
    const float* __restrict__ Wg, const float* __restrict__ bg,
    const float* __restrict__ conv_w, float* __restrict__ inp)
{
    const int blk = blockIdx.x;
    const int b = blk / NODE;
    const int n = blk % NODE;
    const int tid = threadIdx.x;

    __shared__ float sh[HID], sz[HID], sf[HID * 2], sg[HID * HID];

    if (tid < 32) {
        float v = hz[b * HDIM + n * 32 + tid];
        if (tid & 1) sz[tid >> 1] = v;
        else         sh[tid >> 1] = v;
    }
    __syncthreads();

    {
        float acc = bg[tid];
#pragma unroll
        for (int l = 0; l < HID; l++) acc += sz[l] * Wg[l * 256 + tid];
        sg[tid] = tanhf(acc);
    }
    if (tid < 32) {
        float acc = bf[tid];
#pragma unroll
        for (int i = 0; i < HID; i++) acc += sh[i] * Wf[i * 32 + tid];
        sf[tid] = tanhf(acc);
    }
    __syncthreads();

    if (tid < 32) {
        const int i = tid >> 1, c = tid & 1;
        float acc = 0.f;
#pragma unroll
        for (int j = 0; j < HID; j++) acc += sg[i * HID + j] * sf[j * 2 + c];
        const int base = b * IN_DIM + X_DIM + n * 64 + i * 4 + c * 2;
        inp[base]     = sf[i * 2 + c];
        inp[base + 1] = acc;
    }
    if (tid < HID) {
        float v = sv_t[(b * NODE + n) * 2 + 1];
        inp[b * IN_DIM + tid * NODE + n] = conv_w[tid] * v;
    }
}

// ---------------------------------------------------------------------------
__global__ __launch_bounds__(256) void kT(
    const float* __restrict__ inp, float* __restrict__ inpT)
{
    __shared__ float tile[32][33];
    const int i0 = blockIdx.x * 32;
    const int b0 = blockIdx.y * 32;
    const int x = threadIdx.x, y = threadIdx.y;

#pragma unroll
    for (int r = 0; r < 32; r += 8) {
        const int b = b0 + y + r, i = i0 + x;
        if (i < IN_DIM) tile[y + r][x] = inp[b * IN_DIM + i];
    }
    __syncthreads();
#pragma unroll
    for (int r = 0; r < 32; r += 8) {
        const int i = i0 + y + r, b = b0 + x;
        if (i < IN_DIM) inpT[i * BATCH + b] = tile[x][y + r];
    }
}

// ---------------------------------------------------------------------------
// Kernel B: Wih streamed evict-first so it cannot flush the L2-resident
// W_hh columns between kC launches.
// ---------------------------------------------------------------------------
__global__ __launch_bounds__(256) void kB(
    const float* __restrict__ inpT, const float* __restrict__ Wih,
    const float* __restrict__ bih, float* __restrict__ pre)
{
    const int tid = threadIdx.x;
    const int b  = tid & 63;
    const int jg = tid >> 6;
    const int o0 = blockIdx.x * 16 + jg * 4;

    const float* w0 = Wih + (size_t)o0 * IN_DIM;

    float acc[4];
#pragma unroll
    for (int k = 0; k < 4; k++) acc[k] = 0.f;

    for (int i = 0; i < IN_DIM; i += 4) {
        const float x0 = inpT[(i    ) * BATCH + b];
        const float x1 = inpT[(i + 1) * BATCH + b];
        const float x2 = inpT[(i + 2) * BATCH + b];
        const float x3 = inpT[(i + 3) * BATCH + b];
#pragma unroll
        for (int k = 0; k < 4; k++) {
            const float4 w = __ldcs(reinterpret_cast<const float4*>(
                                        w0 + (size_t)k * IN_DIM + i));
            acc[k] += w.x * x0 + w.y * x1 + w.z * x2 + w.w * x3;
        }
    }
#pragma unroll
    for (int k = 0; k < 4; k++)
        pre[b * HDIM + o0 + k] = acc[k] + bih[o0 + k];
}

// ---------------------------------------------------------------------------
// Kernel C (persistent, fp32, 3-tier W storage):
// 138 blocks x 512 threads, 1 CTA/SM, ~218 KB dynamic smem.
// Per block: 48 static rows, 16 warps x 3 rows.
// Tier 1: cols [0,1024)   in smem (cached once per launch, 25.9 MB chip-wide)
// Tier 2: cols [1024,3072) default loads (54.3 MB -> L2-resident)
// Tier 3: cols [3072,6656) __ldcs evict-first streaming (95 MB DRAM/step)
// Streaming tier is issued FIRST each step to front-load DRAM latency.
// ---------------------------------------------------------------------------
extern __shared__ float s_dyn[];

__global__ __launch_bounds__(512, 1) void kC_persist(
    const float* __restrict__ W, const float* __restrict__ pre,
    const float* __restrict__ bhh, float* __restrict__ hz, int t)
{
    float* sh = s_dyn;                 // [0, WSTRIDE)
    float* wc = s_dyn + WSTRIDE;       // 48 rows * 1024 floats
    const int tid  = threadIdx.x;
    const int warp = tid >> 5;
    const int lane = tid & 31;
    const int rbase = blockIdx.x * ROWS_PB + warp * 3;

    const float4* H4 = reinterpret_cast<const float4*>(sh);
    const float4* W0 = reinterpret_cast<const float4*>(W + (size_t)(rbase    ) * WSTRIDE);
    const float4* W1 = reinterpret_cast<const float4*>(W + (size_t)(rbase + 1) * WSTRIDE);
    const float4* W2 = reinterpret_cast<const float4*>(W + (size_t)(rbase + 2) * WSTRIDE);
    const float4* C0 = reinterpret_cast<const float4*>(wc + (size_t)(warp * 3    ) * (CSM4 * 4));
    const float4* C1 = reinterpret_cast<const float4*>(wc + (size_t)(warp * 3 + 1) * (CSM4 * 4));
    const float4* C2 = reinterpret_cast<const float4*>(wc + (size_t)(warp * 3 + 2) * (CSM4 * 4));

    // fill smem W cache once per launch (each warp its own 3 rows)
#pragma unroll
    for (int r = 0; r < 3; r++) {
        const float4* src = reinterpret_cast<const float4*>(
            W + (size_t)(rbase + r) * WSTRIDE);
        float4* dst = reinterpret_cast<float4*>(
            wc + (size_t)(warp * 3 + r) * (CSM4 * 4));
        for (int k = lane; k < CSM4; k += 32) dst[k] = src[k];
    }
    if (tid < WSTRIDE - HDIM) sh[HDIM + tid] = 0.f;   // zero smem h pad
    __syncthreads();

    for (int step = 0; step < BATCH; step++) {
        float a0 = 0.f, a1 = 0.f, a2 = 0.f;

        if (step > 0) {
            const float* hp = hz + (size_t)(step - 1) * HDIM;
            for (int i = tid; i < HDIM; i += 512) sh[i] = __ldcg(hp + i);
            __syncthreads();

            // Tier 3 first: streamed columns [3072,6656) -> 28 lane-strided iters
#pragma unroll 1
            for (int c = 0; c < 28; c += 2) {
                const int k0 = 768 + c * 32 + lane, k1 = k0 + 32;
                const float4 wa0 = __ldcs(&W0[k0]), wa1 = __ldcs(&W0[k1]);
                const float4 wb0 = __ldcs(&W1[k0]), wb1 = __ldcs(&W1[k1]);
                const float4 wc0 = __ldcs(&W2[k0]), wc1 = __ldcs(&W2[k1]);
                const float4 h0  = H4[k0], h1  = H4[k1];
                a0 += wa0.x*h0.x + wa0.y*h0.y + wa0.z*h0.z + wa0.w*h0.w;
                a1 += wb0.x*h0.x + wb0.y*h0.y + wb0.z*h0.z + wb0.w*h0.w;
                a2 += wc0.x*h0.x + wc0.y*h0.y + wc0.z*h0.z + wc0.w*h0.w;
                a0 += wa1.x*h1.x + wa1.y*h1.y + wa1.z*h1.z + wa1.w*h1.w;
                a1 += wb1.x*h1.x + wb1.y*h1.y + wb1.z*h1.z + wb1.w*h1.w;
                a2 += wc1.x*h1.x + wc1.y*h1.y + wc1.z*h1.z + wc1.w*h1.w;
            }
            // Tier 2: L2-resident columns [1024,3072) -> 16 iters
#pragma unroll 1
            for (int c = 0; c < 16; c += 2) {
                const int k0 = 256 + c * 32 + lane, k1 = k0 + 32;
                const float4 wa0 = W0[k0], wa1 = W0[k1];
                const float4 wb0 = W1[k0], wb1 = W1[k1];
                const float4 wc0 = W2[k0], wc1 = W2[k1];
                const float4 h0  = H4[k0], h1  = H4[k1];
                a0 += wa0.x*h0.x + wa0.y*h0.y + wa0.z*h0.z + wa0.w*h0.w;
                a1 += wb0.x*h0.x + wb0.y*h0.y + wb0.z*h0.z + wb0.w*h0.w;
                a2 += wc0.x*h0.x + wc0.y*h0.y + wc0.z*h0.z + wc0.w*h0.w;
                a0 += wa1.x*h1.x + wa1.y*h1.y + wa1.z*h1.z + wa1.w*h1.w;
                a1 += wb1.x*h1.x + wb1.y*h1.y + wb1.z*h1.z + wb1.w*h1.w;
                a2 += wc1.x*h1.x + wc1.y*h1.y + wc1.z*h1.z + wc1.w*h1.w;
            }
            // Tier 1: smem-cached columns [0,1024) -> 8 iters
#pragma unroll 1
            for (int c = 0; c < 8; c += 2) {
                const int k0 = c * 32 + lane, k1 = k0 + 32;
                const float4 wa0 = C0[k0], wa1 = C0[k1];
                const float4 wb0 = C1[k0], wb1 = C1[k1];
                const float4 wc0 = C2[k0], wc1 = C2[k1];
                const float4 h0  = H4[k0], h1  = H4[k1];
                a0 += wa0.x*h0.x + wa0.y*h0.y + wa0.z*h0.z + wa0.w*h0.w;
                a1 += wb0.x*h0.x + wb0.y*h0.y + wb0.z*h0.z + wb0.w*h0.w;
                a2 += wc0.x*h0.x + wc0.y*h0.y + wc0.z*h0.z + wc0.w*h0.w;
                a0 += wa1.x*h1.x + wa1.y*h1.y + wa1.z*h1.z + wa1.w*h1.w;
                a1 += wb1.x*h1.x + wb1.y*h1.y + wb1.z*h1.z + wb1.w*h1.w;
                a2 += wc1.x*h1.x + wc1.y*h1.y + wc1.z*h1.z + wc1.w*h1.w;
            }
        }

#pragma unroll
        for (int s = 16; s; s >>= 1) {
            a0 += __shfl_xor_sync(0xffffffffu, a0, s);
            a1 += __shfl_xor_sync(0xffffffffu, a1, s);
            a2 += __shfl_xor_sync(0xffffffffu, a2, s);
        }
        if (lane == 0) {
            const float* pre_b = pre + (size_t)step * HDIM;
            float* hout = hz + (size_t)step * HDIM;
            __stcg(hout + rbase    , tanhf(a0 + pre_b[rbase    ] + bhh[rbase    ]));
            __stcg(hout + rbase + 1, tanhf(a1 + pre_b[rbase + 1] + bhh[rbase + 1]));
            __stcg(hout + rbase + 2, tanhf(a2 + pre_b[rbase + 2] + bhh[rbase + 2]));
        }

        // grid barrier (also protects smem h WAR for next step's staging)
        __threadfence();
        __syncthreads();
        if (tid == 0) {
            const unsigned k = (unsigned)(t * BATCH + step + 1);
            const unsigned old = atomicAdd(&g_bar[0], 1u);
            if (old == k * NB - 1u) {
                atomicExch(&g_bar[1], k);
            } else {
                while (atomicAdd(&g_bar[1], 0u) < k) __nanosleep(64);
            }
        }
        __syncthreads();
    }
}

// ---------------------------------------------------------------------------
extern "C" void kernel_launch(void* const* d_in, const int* in_sizes, int n_in,
                              void* d_out, int out_size)
{
    const float* sv    = (const float*)d_in[0];
    const float* init0 = (const float*)d_in[1];
    const float* Wf    = (const float*)d_in[2];
    const float* bf    = (const float*)d_in[3];
    const float* Wg    = (const float*)d_in[4];
    const float* bg    = (const float*)d_in[5];
    const float* cw    = (const float*)d_in[6];
    const float* Wih   = (const float*)d_in[7];
    const float* bih   = (const float*)d_in[8];
    const float* Whh   = (const float*)d_in[9];
    const float* bhh   = (const float*)d_in[10];

    float *hz, *inp, *inpT, *pre, *wpad;
    unsigned* bar;
    cudaGetSymbolAddress((void**)&hz,   g_hz);
    cudaGetSymbolAddress((void**)&inp,  g_inp);
    cudaGetSymbolAddress((void**)&inpT, g_inpT);
    cudaGetSymbolAddress((void**)&pre,  g_pre);
    cudaGetSymbolAddress((void**)&wpad, g_w);
    cudaGetSymbolAddress((void**)&bar,  g_bar);

    static int smem_set = 0;
    if (!smem_set) {
        cudaFuncSetAttribute(kC_persist,
                             cudaFuncAttributeMaxDynamicSharedMemorySize,
                             SMEM_BYTES);
        smem_set = 1;
    }

    cudaMemsetAsync(bar, 0, 2 * sizeof(unsigned));
    kH<<<HDIM, 256>>>(Whh);
    cudaMemcpyAsync(hz, init0, (size_t)BATCH * HDIM * sizeof(float),
                    cudaMemcpyDeviceToDevice);

    for (int t = 0; t < T_STEPS; t++) {
        kA<<<BATCH * NODE, 256>>>(hz, sv + (size_t)t * BATCH * NODE * 2,
                                  Wf, bf, Wg, bg, cw, inp);
        {
            dim3 tb(32, 8), tg((IN_DIM + 31) / 32, BATCH / 32);
            kT<<<tg, tb>>>(inp, inpT);
        }
        kB<<<HDIM / 16, 256>>>(inpT, Wih, bih, pre);

        kC_persist<<<NB, 512, SMEM_BYTES>>>(wpad, pre, bhh, hz, t);
    }

    cudaMemcpyAsync(d_out, hz, (size_t)BATCH * HDIM * sizeof(float),
                    cudaMemcpyDeviceToDevice);
}